// round 4
// baseline (speedup 1.0000x reference)
#include <cuda_runtime.h>
#include <math.h>
#include <stdint.h>

#define B_  4
#define S_  2048
#define D_  1024
#define H_  16
#define HD_ 64
#define MS_ (B_*S_)   // 8192

// Scratch (static device globals — no allocation)
__device__ float g_Q[(size_t)MS_ * D_];
__device__ float g_K[(size_t)MS_ * D_];
__device__ float g_V[(size_t)MS_ * D_];
__device__ float g_C[(size_t)MS_ * D_];
__device__ float g_WT[4][(size_t)D_ * D_];   // transposed weights [n][k]

// ---------------------------------------------------------------------------
// tf32 helpers (sm_80+ ISA — compiles for plain sm_103 target)
// ---------------------------------------------------------------------------
__device__ __forceinline__ float f2tf(float f) {
    uint32_t u;
    asm("cvt.rna.tf32.f32 %0, %1;" : "=r"(u) : "f"(f));
    return __uint_as_float(u);
}

__device__ __forceinline__ void mma_tf32(float* d, const uint32_t* a, const uint32_t* b) {
    asm volatile(
        "mma.sync.aligned.m16n8k8.row.col.f32.tf32.tf32.f32 "
        "{%0,%1,%2,%3}, {%4,%5,%6,%7}, {%8,%9}, {%0,%1,%2,%3};"
        : "+f"(d[0]), "+f"(d[1]), "+f"(d[2]), "+f"(d[3])
        : "r"(a[0]), "r"(a[1]), "r"(a[2]), "r"(a[3]),
          "r"(b[0]), "r"(b[1]));
}

// ===========================================================================
// Weight transpose: out[n][k] = in[k][n], 1024x1024
// ===========================================================================
__global__ __launch_bounds__(256) void transpose1024(
    const float* __restrict__ in, float* __restrict__ out)
{
    __shared__ float t[32][33];
    int x = blockIdx.x * 32 + threadIdx.x;
    int y = blockIdx.y * 32 + threadIdx.y;
#pragma unroll
    for (int j = 0; j < 32; j += 8)
        t[threadIdx.y + j][threadIdx.x] = in[(size_t)(y + j) * D_ + x];
    __syncthreads();
    x = blockIdx.y * 32 + threadIdx.x;
    y = blockIdx.x * 32 + threadIdx.y;
#pragma unroll
    for (int j = 0; j < 32; j += 8)
        out[(size_t)(y + j) * D_ + x] = t[threadIdx.x][threadIdx.y + j];
}

// ===========================================================================
// tf32 MMA GEMM + bias: C[M,N] = A[M,K] @ BT[N,K]^T + bias[N]
// 128x128 tile, BK=32, 256 threads = 8 warps (2 x 4), warp tile 64x32.
// ===========================================================================
__global__ __launch_bounds__(256) void mma_gemm_bias(
    const float* __restrict__ A, const float* __restrict__ BT,
    const float* __restrict__ bias, float* __restrict__ C,
    int M, int N, int K)
{
    __shared__ float As[128][36];   // [m][k]
    __shared__ float Bs[128][36];   // [n][k]

    int tid  = threadIdx.x;
    int lane = tid & 31, warp = tid >> 5;
    int g = lane >> 2, t = lane & 3;
    int wm = warp >> 2, wn = warp & 3;

    int m0 = blockIdx.y * 128, n0 = blockIdx.x * 128;

    float acc[4][4][4];
#pragma unroll
    for (int i = 0; i < 4; i++)
#pragma unroll
        for (int j = 0; j < 4; j++)
#pragma unroll
            for (int r = 0; r < 4; r++) acc[i][j][r] = 0.f;

    for (int k0 = 0; k0 < K; k0 += 32) {
        __syncthreads();
#pragma unroll
        for (int p = 0; p < 4; p++) {
            int f4 = p * 256 + tid;
            int r = f4 >> 3, c4 = (f4 & 7) * 4;
            float4 va = *(const float4*)(A + (size_t)(m0 + r) * K + k0 + c4);
            As[r][c4 + 0] = f2tf(va.x); As[r][c4 + 1] = f2tf(va.y);
            As[r][c4 + 2] = f2tf(va.z); As[r][c4 + 3] = f2tf(va.w);
            float4 vb = *(const float4*)(BT + (size_t)(n0 + r) * K + k0 + c4);
            Bs[r][c4 + 0] = f2tf(vb.x); Bs[r][c4 + 1] = f2tf(vb.y);
            Bs[r][c4 + 2] = f2tf(vb.z); Bs[r][c4 + 3] = f2tf(vb.w);
        }
        __syncthreads();

#pragma unroll
        for (int kk = 0; kk < 32; kk += 8) {
            uint32_t af[4][4], bf[4][2];
#pragma unroll
            for (int mi = 0; mi < 4; mi++) {
                int mr = wm * 64 + mi * 16 + g;
                af[mi][0] = __float_as_uint(As[mr][kk + t]);
                af[mi][1] = __float_as_uint(As[mr + 8][kk + t]);
                af[mi][2] = __float_as_uint(As[mr][kk + t + 4]);
                af[mi][3] = __float_as_uint(As[mr + 8][kk + t + 4]);
            }
#pragma unroll
            for (int ni = 0; ni < 4; ni++) {
                int nr = wn * 32 + ni * 8 + g;
                bf[ni][0] = __float_as_uint(Bs[nr][kk + t]);
                bf[ni][1] = __float_as_uint(Bs[nr][kk + t + 4]);
            }
#pragma unroll
            for (int mi = 0; mi < 4; mi++)
#pragma unroll
                for (int ni = 0; ni < 4; ni++)
                    mma_tf32(acc[mi][ni], af[mi], bf[ni]);
        }
    }

#pragma unroll
    for (int mi = 0; mi < 4; mi++) {
        int row = m0 + wm * 64 + mi * 16 + g;
#pragma unroll
        for (int ni = 0; ni < 4; ni++) {
            int col = n0 + wn * 32 + ni * 8 + 2 * t;
            float2 b2 = *(const float2*)(bias + col);
            float2 o0, o1;
            o0.x = acc[mi][ni][0] + b2.x; o0.y = acc[mi][ni][1] + b2.y;
            o1.x = acc[mi][ni][2] + b2.x; o1.y = acc[mi][ni][3] + b2.y;
            *(float2*)(C + (size_t)row * N + col)       = o0;
            *(float2*)(C + (size_t)(row + 8) * N + col) = o1;
        }
    }
}

// ===========================================================================
// Fused attention: per CTA = 16 query rows x full 2048 keys for one (b,h).
// Phase 1: S = (Q.K^T)/8 via tf32 MMA into smem [16][2048] fp32
// Phase 2: exact softmax on smem rows; write normalized attn to global once;
//          store tf32-rounded probs back to smem
// Phase 3: context = P @ V via tf32 MMA (V tiles L2-resident); write g_C
// grid (128 qtiles, 64 bh), 256 threads, ~171KB dynamic smem.
// ===========================================================================
#define SROW 2056                      // padded row stride (floats)
#define SMEM_S_F   (16 * SROW)         // 32896 floats
#define SMEM_KV_F  (128 * 68)          // 8704 floats (== 64*136)
#define SMEM_Q_F   (16 * 68)           // 1088 floats
#define FUSED_SMEM ((SMEM_S_F + SMEM_KV_F + SMEM_Q_F) * 4)

__global__ __launch_bounds__(256) void fused_attn(float* __restrict__ attn)
{
    extern __shared__ float fsm[];
    float* Sb = fsm;                        // [16][SROW]
    float* KV = fsm + SMEM_S_F;             // K: [128][68] / V^T: [64][136]
    float* Qs = fsm + SMEM_S_F + SMEM_KV_F; // [16][68]

    int tid  = threadIdx.x;
    int lane = tid & 31, warp = tid >> 5;
    int g = lane >> 2, t = lane & 3;

    int bh = blockIdx.y;
    int b = bh >> 4, h = bh & 15;
    int q0 = blockIdx.x * 16;

    const float* Qg = g_Q + ((size_t)b * S_ + q0) * D_ + h * HD_;
    const float* Kg = g_K + (size_t)b * S_ * D_ + h * HD_;
    const float* Vg = g_V + (size_t)b * S_ * D_ + h * HD_;

    // ---- load Q tile (16 x 64), tf32-rounded ----
    {
        int r = tid >> 4, c4 = (tid & 15) * 4;
        float4 v = *(const float4*)(Qg + (size_t)r * D_ + c4);
        Qs[r * 68 + c4 + 0] = f2tf(v.x); Qs[r * 68 + c4 + 1] = f2tf(v.y);
        Qs[r * 68 + c4 + 2] = f2tf(v.z); Qs[r * 68 + c4 + 3] = f2tf(v.w);
    }

    // ================= Phase 1: scores =================
    const float scale = 0.125f;
    for (int kt = 0; kt < 16; kt++) {
        __syncthreads();   // prior MMA reads of KV done
        // load K tile: 128 keys x 64 dims
#pragma unroll
        for (int p = 0; p < 8; p++) {
            int f4 = p * 256 + tid;
            int r = f4 >> 4, c4 = (f4 & 15) * 4;
            float4 v = *(const float4*)(Kg + (size_t)(kt * 128 + r) * D_ + c4);
            KV[r * 68 + c4 + 0] = f2tf(v.x); KV[r * 68 + c4 + 1] = f2tf(v.y);
            KV[r * 68 + c4 + 2] = f2tf(v.z); KV[r * 68 + c4 + 3] = f2tf(v.w);
        }
        __syncthreads();

        float acc[2][4];
#pragma unroll
        for (int i = 0; i < 2; i++)
#pragma unroll
            for (int r = 0; r < 4; r++) acc[i][r] = 0.f;

#pragma unroll
        for (int kk = 0; kk < 64; kk += 8) {
            uint32_t af[4], bf[2][2];
            af[0] = __float_as_uint(Qs[g * 68 + kk + t]);
            af[1] = __float_as_uint(Qs[(g + 8) * 68 + kk + t]);
            af[2] = __float_as_uint(Qs[g * 68 + kk + t + 4]);
            af[3] = __float_as_uint(Qs[(g + 8) * 68 + kk + t + 4]);
#pragma unroll
            for (int ni = 0; ni < 2; ni++) {
                int nr = warp * 16 + ni * 8 + g;
                bf[ni][0] = __float_as_uint(KV[nr * 68 + kk + t]);
                bf[ni][1] = __float_as_uint(KV[nr * 68 + kk + t + 4]);
            }
#pragma unroll
            for (int ni = 0; ni < 2; ni++)
                mma_tf32(acc[ni], af, bf[ni]);
        }
        // store S fragments (scaled)
#pragma unroll
        for (int ni = 0; ni < 2; ni++) {
            int col = kt * 128 + warp * 16 + ni * 8 + 2 * t;
            float2 o0, o1;
            o0.x = acc[ni][0] * scale; o0.y = acc[ni][1] * scale;
            o1.x = acc[ni][2] * scale; o1.y = acc[ni][3] * scale;
            *(float2*)(Sb + (size_t)g * SROW + col)       = o0;
            *(float2*)(Sb + (size_t)(g + 8) * SROW + col) = o1;
        }
    }
    __syncthreads();

    // ================= Phase 2: softmax =================
    // warp w handles rows 2w and 2w+1; full row resident in registers
    float* attn_bh = attn + (size_t)bh * S_ * S_;
#pragma unroll
    for (int rr = 0; rr < 2; rr++) {
        int row = warp * 2 + rr;
        float* Sr = Sb + (size_t)row * SROW;

        float4 v[16];
        float m = -3.4e38f;
#pragma unroll
        for (int i = 0; i < 16; i++) {
            v[i] = *(float4*)(Sr + lane * 4 + i * 128);
            m = fmaxf(m, fmaxf(fmaxf(v[i].x, v[i].y), fmaxf(v[i].z, v[i].w)));
        }
#pragma unroll
        for (int o = 16; o > 0; o >>= 1)
            m = fmaxf(m, __shfl_xor_sync(0xffffffffu, m, o));

        float s = 0.f;
#pragma unroll
        for (int i = 0; i < 16; i++) {
            v[i].x = __expf(v[i].x - m); v[i].y = __expf(v[i].y - m);
            v[i].z = __expf(v[i].z - m); v[i].w = __expf(v[i].w - m);
            s += (v[i].x + v[i].y) + (v[i].z + v[i].w);
        }
#pragma unroll
        for (int o = 16; o > 0; o >>= 1)
            s += __shfl_xor_sync(0xffffffffu, s, o);
        float rinv = 1.0f / s;

        float* arow = attn_bh + (size_t)(q0 + row) * S_;
#pragma unroll
        for (int i = 0; i < 16; i++) {
            float4 p;
            p.x = v[i].x * rinv; p.y = v[i].y * rinv;
            p.z = v[i].z * rinv; p.w = v[i].w * rinv;
            *(float4*)(arow + lane * 4 + i * 128) = p;   // exact fp32 to output
            Sr[lane * 4 + i * 128 + 0] = f2tf(p.x);      // tf32 for context MMA
            Sr[lane * 4 + i * 128 + 1] = f2tf(p.y);
            Sr[lane * 4 + i * 128 + 2] = f2tf(p.z);
            Sr[lane * 4 + i * 128 + 3] = f2tf(p.w);
        }
    }

    // ================= Phase 3: context =================
    float acco[4] = {0.f, 0.f, 0.f, 0.f};   // warp w -> out cols 8w..8w+7
    for (int kt = 0; kt < 16; kt++) {
        __syncthreads();   // prior MMA reads of KV done (or phase-2 writes)
        // load V tile transposed: Vt[hd][kpos] = V[kt*128+kpos][hd]
#pragma unroll
        for (int p = 0; p < 8; p++) {
            int f4 = p * 256 + tid;
            int kr = f4 >> 4, c4 = (f4 & 15) * 4;
            float4 v = *(const float4*)(Vg + (size_t)(kt * 128 + kr) * D_ + c4);
            KV[(c4 + 0) * 136 + kr] = f2tf(v.x);
            KV[(c4 + 1) * 136 + kr] = f2tf(v.y);
            KV[(c4 + 2) * 136 + kr] = f2tf(v.z);
            KV[(c4 + 3) * 136 + kr] = f2tf(v.w);
        }
        __syncthreads();

        int kb = kt * 128;
#pragma unroll
        for (int kk = 0; kk < 128; kk += 8) {
            uint32_t af[4], bf[2];
            af[0] = __float_as_uint(Sb[(size_t)g * SROW + kb + kk + t]);
            af[1] = __float_as_uint(Sb[(size_t)(g + 8) * SROW + kb + kk + t]);
            af[2] = __float_as_uint(Sb[(size_t)g * SROW + kb + kk + t + 4]);
            af[3] = __float_as_uint(Sb[(size_t)(g + 8) * SROW + kb + kk + t + 4]);
            int nr = warp * 8 + g;
            bf[0] = __float_as_uint(KV[nr * 136 + kk + t]);
            bf[1] = __float_as_uint(KV[nr * 136 + kk + t + 4]);
            mma_tf32(acco, af, bf);
        }
    }

    // write context: rows q0+g, q0+g+8; cols h*64 + 8*warp + 2t
    float* Cb = g_C + ((size_t)b * S_ + q0) * D_ + h * HD_;
    int col = warp * 8 + 2 * t;
    float2 o0, o1;
    o0.x = acco[0]; o0.y = acco[1];
    o1.x = acco[2]; o1.y = acco[3];
    *(float2*)(Cb + (size_t)g * D_ + col)       = o0;
    *(float2*)(Cb + (size_t)(g + 8) * D_ + col) = o1;
}

// ---------------------------------------------------------------------------
extern "C" void kernel_launch(void* const* d_in, const int* in_sizes, int n_in,
                              void* d_out, int out_size)
{
    const float* q  = (const float*)d_in[0];
    const float* k  = (const float*)d_in[1];
    const float* v  = (const float*)d_in[2];
    const float* Wq = (const float*)d_in[3];
    const float* bq = (const float*)d_in[4];
    const float* Wk = (const float*)d_in[5];
    const float* bk = (const float*)d_in[6];
    const float* Wv = (const float*)d_in[7];
    const float* bv = (const float*)d_in[8];
    const float* Wo = (const float*)d_in[9];
    const float* bo = (const float*)d_in[10];

    float* out  = (float*)d_out;
    float* attn = out + (size_t)MS_ * D_;   // tuple order: (output, attention)

    float *pQ, *pK, *pV, *pC, *pWT;
    cudaGetSymbolAddress((void**)&pQ, g_Q);
    cudaGetSymbolAddress((void**)&pK, g_K);
    cudaGetSymbolAddress((void**)&pV, g_V);
    cudaGetSymbolAddress((void**)&pC, g_C);
    cudaGetSymbolAddress((void**)&pWT, g_WT);

    cudaFuncSetAttribute(fused_attn,
                         cudaFuncAttributeMaxDynamicSharedMemorySize, FUSED_SMEM);

    float* WTq = pWT + 0 * (size_t)D_ * D_;
    float* WTk = pWT + 1 * (size_t)D_ * D_;
    float* WTv = pWT + 2 * (size_t)D_ * D_;
    float* WTo = pWT + 3 * (size_t)D_ * D_;

    dim3 tb(32, 8), tg(32, 32);
    transpose1024<<<tg, tb>>>(Wq, WTq);
    transpose1024<<<tg, tb>>>(Wk, WTk);
    transpose1024<<<tg, tb>>>(Wv, WTv);
    transpose1024<<<tg, tb>>>(Wo, WTo);

    dim3 gp(D_ / 128, MS_ / 128);  // (8, 64)
    mma_gemm_bias<<<gp, 256>>>(q, WTq, bq, pQ, MS_, D_, D_);
    mma_gemm_bias<<<gp, 256>>>(k, WTk, bk, pK, MS_, D_, D_);
    mma_gemm_bias<<<gp, 256>>>(v, WTv, bv, pV, MS_, D_, D_);

    fused_attn<<<dim3(S_ / 16, B_ * H_), 256, FUSED_SMEM>>>(attn);

    mma_gemm_bias<<<gp, 256>>>(pC, WTo, bo, out, MS_, D_, D_);
}

// round 5
// speedup vs baseline: 2.6409x; 2.6409x over previous
#include <cuda_runtime.h>
#include <math.h>
#include <stdint.h>

#define B_  4
#define S_  2048
#define D_  1024
#define H_  16
#define HD_ 64
#define MS_ (B_*S_)   // 8192

// Scratch (static device globals — no allocation)
__device__ float g_Q[(size_t)MS_ * D_];
__device__ float g_K[(size_t)MS_ * D_];
__device__ float g_V[(size_t)MS_ * D_];
__device__ float g_C[(size_t)MS_ * D_];
__device__ float g_WT[4][(size_t)D_ * D_];   // transposed + tf32-rounded weights

// ---------------------------------------------------------------------------
// tf32 helpers (sm_80+ ISA — compiles for plain sm_103 target)
// ---------------------------------------------------------------------------
__device__ __forceinline__ float f2tf(float f) {
    uint32_t u;
    asm("cvt.rna.tf32.f32 %0, %1;" : "=r"(u) : "f"(f));
    return __uint_as_float(u);
}

__device__ __forceinline__ void mma_tf32(float* d, const uint32_t* a, const uint32_t* b) {
    asm volatile(
        "mma.sync.aligned.m16n8k8.row.col.f32.tf32.tf32.f32 "
        "{%0,%1,%2,%3}, {%4,%5,%6,%7}, {%8,%9}, {%0,%1,%2,%3};"
        : "+f"(d[0]), "+f"(d[1]), "+f"(d[2]), "+f"(d[3])
        : "r"(a[0]), "r"(a[1]), "r"(a[2]), "r"(a[3]),
          "r"(b[0]), "r"(b[1]));
}

// ===========================================================================
// Weight transpose + tf32 pre-round: out[n][k] = tf32(in[k][n])
// ===========================================================================
__global__ __launch_bounds__(256) void transpose1024(
    const float* __restrict__ in, float* __restrict__ out)
{
    __shared__ float t[32][33];
    int x = blockIdx.x * 32 + threadIdx.x;
    int y = blockIdx.y * 32 + threadIdx.y;
#pragma unroll
    for (int j = 0; j < 32; j += 8)
        t[threadIdx.y + j][threadIdx.x] = in[(size_t)(y + j) * D_ + x];
    __syncthreads();
    x = blockIdx.y * 32 + threadIdx.x;
    y = blockIdx.x * 32 + threadIdx.y;
#pragma unroll
    for (int j = 0; j < 32; j += 8)
        out[(size_t)(y + j) * D_ + x] = f2tf(t[threadIdx.x][threadIdx.y + j]);
}

// ===========================================================================
// Shared 128x128xK MMA mainloop, BK=32, register double-buffered.
// A pre-offset to tile row 0 (row stride lda); BT pre-offset (row stride ldb).
// ===========================================================================
template<bool CVTA, bool CVTB>
__device__ __forceinline__ void gemm_main(
    const float* __restrict__ A, const float* __restrict__ BT,
    int K, int lda, int ldb,
    float (&As)[128][36], float (&Bs)[128][36],
    float (&acc)[4][4][4])
{
    int tid  = threadIdx.x;
    int lane = tid & 31, warp = tid >> 5;
    int g = lane >> 2, t = lane & 3;
    int wm = warp >> 2, wn = warp & 3;

    float4 pa[4], pb[4];
#pragma unroll
    for (int p = 0; p < 4; p++) {
        int f4 = p * 256 + tid;
        int r = f4 >> 3, c4 = (f4 & 7) * 4;
        pa[p] = *(const float4*)(A + (size_t)r * lda + c4);
        pb[p] = *(const float4*)(BT + (size_t)r * ldb + c4);
    }

    int NT = K / 32;
    for (int it = 0; it < NT; it++) {
#pragma unroll
        for (int p = 0; p < 4; p++) {
            int f4 = p * 256 + tid;
            int r = f4 >> 3, c4 = (f4 & 7) * 4;
            As[r][c4 + 0] = CVTA ? f2tf(pa[p].x) : pa[p].x;
            As[r][c4 + 1] = CVTA ? f2tf(pa[p].y) : pa[p].y;
            As[r][c4 + 2] = CVTA ? f2tf(pa[p].z) : pa[p].z;
            As[r][c4 + 3] = CVTA ? f2tf(pa[p].w) : pa[p].w;
            Bs[r][c4 + 0] = CVTB ? f2tf(pb[p].x) : pb[p].x;
            Bs[r][c4 + 1] = CVTB ? f2tf(pb[p].y) : pb[p].y;
            Bs[r][c4 + 2] = CVTB ? f2tf(pb[p].z) : pb[p].z;
            Bs[r][c4 + 3] = CVTB ? f2tf(pb[p].w) : pb[p].w;
        }
        __syncthreads();

        if (it + 1 < NT) {
            int k0 = (it + 1) * 32;
#pragma unroll
            for (int p = 0; p < 4; p++) {
                int f4 = p * 256 + tid;
                int r = f4 >> 3, c4 = (f4 & 7) * 4;
                pa[p] = *(const float4*)(A + (size_t)r * lda + k0 + c4);
                pb[p] = *(const float4*)(BT + (size_t)r * ldb + k0 + c4);
            }
        }

#pragma unroll
        for (int kk = 0; kk < 32; kk += 8) {
            uint32_t af[4][4], bf[4][2];
#pragma unroll
            for (int mi = 0; mi < 4; mi++) {
                int mr = wm * 64 + mi * 16 + g;
                af[mi][0] = __float_as_uint(As[mr][kk + t]);
                af[mi][1] = __float_as_uint(As[mr + 8][kk + t]);
                af[mi][2] = __float_as_uint(As[mr][kk + t + 4]);
                af[mi][3] = __float_as_uint(As[mr + 8][kk + t + 4]);
            }
#pragma unroll
            for (int ni = 0; ni < 4; ni++) {
                int nr = wn * 32 + ni * 8 + g;
                bf[ni][0] = __float_as_uint(Bs[nr][kk + t]);
                bf[ni][1] = __float_as_uint(Bs[nr][kk + t + 4]);
            }
#pragma unroll
            for (int mi = 0; mi < 4; mi++)
#pragma unroll
                for (int ni = 0; ni < 4; ni++)
                    mma_tf32(acc[mi][ni], af[mi], bf[ni]);
        }
        __syncthreads();
    }
}

// ===========================================================================
// Fused Q/K/V projection GEMMs (grid.z selects tensor).
// A raw fp32 (cvt at STS); W pre-rounded. Epilogue: tf32(acc + bias).
// ===========================================================================
__global__ __launch_bounds__(256) void qkv_gemm(
    const float* __restrict__ Aq, const float* __restrict__ Ak,
    const float* __restrict__ Av,
    const float* __restrict__ Wq, const float* __restrict__ Wk,
    const float* __restrict__ Wv,
    const float* __restrict__ bq, const float* __restrict__ bk,
    const float* __restrict__ bv,
    float* __restrict__ Cq, float* __restrict__ Ck, float* __restrict__ Cv)
{
    __shared__ float As[128][36];
    __shared__ float Bs[128][36];

    int z = blockIdx.z;
    const float* A    = (z == 0) ? Aq : (z == 1) ? Ak : Av;
    const float* BT   = (z == 0) ? Wq : (z == 1) ? Wk : Wv;
    const float* bias = (z == 0) ? bq : (z == 1) ? bk : bv;
    float*       C    = (z == 0) ? Cq : (z == 1) ? Ck : Cv;

    int m0 = blockIdx.y * 128, n0 = blockIdx.x * 128;

    float acc[4][4][4];
#pragma unroll
    for (int i = 0; i < 4; i++)
#pragma unroll
        for (int j = 0; j < 4; j++)
#pragma unroll
            for (int r = 0; r < 4; r++) acc[i][j][r] = 0.f;

    gemm_main<true, false>(A + (size_t)m0 * D_, BT + (size_t)n0 * D_,
                           D_, D_, D_, As, Bs, acc);

    int lane = threadIdx.x & 31, warp = threadIdx.x >> 5;
    int g = lane >> 2, t = lane & 3;
    int wm = warp >> 2, wn = warp & 3;
#pragma unroll
    for (int mi = 0; mi < 4; mi++) {
        int row = m0 + wm * 64 + mi * 16 + g;
#pragma unroll
        for (int ni = 0; ni < 4; ni++) {
            int col = n0 + wn * 32 + ni * 8 + 2 * t;
            float2 b2 = *(const float2*)(bias + col);
            float2 o0, o1;
            o0.x = f2tf(acc[mi][ni][0] + b2.x); o0.y = f2tf(acc[mi][ni][1] + b2.y);
            o1.x = f2tf(acc[mi][ni][2] + b2.x); o1.y = f2tf(acc[mi][ni][3] + b2.y);
            *(float2*)(C + (size_t)row * D_ + col)       = o0;
            *(float2*)(C + (size_t)(row + 8) * D_ + col) = o1;
        }
    }
}

// ===========================================================================
// Output projection GEMM: A (g_C) and W both pre-rounded; fp32 epilogue.
// ===========================================================================
__global__ __launch_bounds__(256) void out_gemm(
    const float* __restrict__ A, const float* __restrict__ BT,
    const float* __restrict__ bias, float* __restrict__ C)
{
    __shared__ float As[128][36];
    __shared__ float Bs[128][36];

    int m0 = blockIdx.y * 128, n0 = blockIdx.x * 128;

    float acc[4][4][4];
#pragma unroll
    for (int i = 0; i < 4; i++)
#pragma unroll
        for (int j = 0; j < 4; j++)
#pragma unroll
            for (int r = 0; r < 4; r++) acc[i][j][r] = 0.f;

    gemm_main<false, false>(A + (size_t)m0 * D_, BT + (size_t)n0 * D_,
                            D_, D_, D_, As, Bs, acc);

    int lane = threadIdx.x & 31, warp = threadIdx.x >> 5;
    int g = lane >> 2, t = lane & 3;
    int wm = warp >> 2, wn = warp & 3;
#pragma unroll
    for (int mi = 0; mi < 4; mi++) {
        int row = m0 + wm * 64 + mi * 16 + g;
#pragma unroll
        for (int ni = 0; ni < 4; ni++) {
            int col = n0 + wn * 32 + ni * 8 + 2 * t;
            float2 b2 = *(const float2*)(bias + col);
            float2 o0, o1;
            o0.x = acc[mi][ni][0] + b2.x; o0.y = acc[mi][ni][1] + b2.y;
            o1.x = acc[mi][ni][2] + b2.x; o1.y = acc[mi][ni][3] + b2.y;
            *(float2*)(C + (size_t)row * D_ + col)       = o0;
            *(float2*)(C + (size_t)(row + 8) * D_ + col) = o1;
        }
    }
}

// ===========================================================================
// Scores: attn[bh,q,k] = (Q . K)/8 — Q,K pre-rounded tf32, no cvt needed.
// grid (16,16,64).
// ===========================================================================
__global__ __launch_bounds__(256) void scores_mma(float* __restrict__ attn)
{
    __shared__ float As[128][36];
    __shared__ float Bs[128][36];

    int bh = blockIdx.z;
    int b = bh >> 4, h = bh & 15;
    int m0 = blockIdx.y * 128, n0 = blockIdx.x * 128;

    const float* Qb = g_Q + ((size_t)b * S_ + m0) * D_ + h * HD_;
    const float* Kb = g_K + ((size_t)b * S_ + n0) * D_ + h * HD_;

    float acc[4][4][4];
#pragma unroll
    for (int i = 0; i < 4; i++)
#pragma unroll
        for (int j = 0; j < 4; j++)
#pragma unroll
            for (int r = 0; r < 4; r++) acc[i][j][r] = 0.f;

    gemm_main<false, false>(Qb, Kb, HD_, D_, D_, As, Bs, acc);

    int lane = threadIdx.x & 31, warp = threadIdx.x >> 5;
    int g = lane >> 2, t = lane & 3;
    int wm = warp >> 2, wn = warp & 3;
    const float scale = 0.125f;
    size_t base = (size_t)bh * S_ * S_;
#pragma unroll
    for (int mi = 0; mi < 4; mi++) {
        int row = m0 + wm * 64 + mi * 16 + g;
#pragma unroll
        for (int ni = 0; ni < 4; ni++) {
            int col = n0 + wn * 32 + ni * 8 + 2 * t;
            float2 o0, o1;
            o0.x = acc[mi][ni][0] * scale; o0.y = acc[mi][ni][1] * scale;
            o1.x = acc[mi][ni][2] * scale; o1.y = acc[mi][ni][3] * scale;
            *(float2*)(attn + base + (size_t)row * S_ + col)       = o0;
            *(float2*)(attn + base + (size_t)(row + 8) * S_ + col) = o1;
        }
    }
}

// ===========================================================================
// Context: C = P @ V, 128(q) x 64(hd) tile, BK=32, double-buffered.
// P (probs) cvt at STS; V pre-rounded. Epilogue writes tf32(acc) to g_C.
// grid (16, 64).
// ===========================================================================
__global__ __launch_bounds__(256) void context_mma(const float* __restrict__ attn)
{
    __shared__ float As[128][36];   // probs [q][kpos]
    __shared__ float Vs[64][36];    // V^T   [hd][kpos]

    int tid  = threadIdx.x;
    int lane = tid & 31, warp = tid >> 5;
    int g = lane >> 2, t = lane & 3;
    int wm = warp >> 1, wn = warp & 1;   // 4 x 2

    int bh = blockIdx.y;
    int b = bh >> 4, h = bh & 15;
    int m0 = blockIdx.x * 128;
    const float* Ab = attn + (size_t)bh * S_ * S_ + (size_t)m0 * S_;
    const float* Vb = g_V + (size_t)b * S_ * D_ + h * HD_;

    float acc[2][4][4];
#pragma unroll
    for (int i = 0; i < 2; i++)
#pragma unroll
        for (int j = 0; j < 4; j++)
#pragma unroll
            for (int r = 0; r < 4; r++) acc[i][j][r] = 0.f;

    float4 pa[4], pv[2];
#pragma unroll
    for (int p = 0; p < 4; p++) {
        int f4 = p * 256 + tid;
        int r = f4 >> 3, c4 = (f4 & 7) * 4;
        pa[p] = *(const float4*)(Ab + (size_t)r * S_ + c4);
    }
#pragma unroll
    for (int p = 0; p < 2; p++) {
        int f4 = p * 256 + tid;
        int kr = f4 >> 4, c4 = (f4 & 15) * 4;
        pv[p] = *(const float4*)(Vb + (size_t)kr * D_ + c4);
    }

    for (int it = 0; it < S_ / 32; it++) {
#pragma unroll
        for (int p = 0; p < 4; p++) {
            int f4 = p * 256 + tid;
            int r = f4 >> 3, c4 = (f4 & 7) * 4;
            As[r][c4 + 0] = f2tf(pa[p].x); As[r][c4 + 1] = f2tf(pa[p].y);
            As[r][c4 + 2] = f2tf(pa[p].z); As[r][c4 + 3] = f2tf(pa[p].w);
        }
#pragma unroll
        for (int p = 0; p < 2; p++) {
            int f4 = p * 256 + tid;
            int kr = f4 >> 4, c4 = (f4 & 15) * 4;
            Vs[c4 + 0][kr] = pv[p].x; Vs[c4 + 1][kr] = pv[p].y;
            Vs[c4 + 2][kr] = pv[p].z; Vs[c4 + 3][kr] = pv[p].w;
        }
        __syncthreads();

        if (it + 1 < S_ / 32) {
            int k0 = (it + 1) * 32;
#pragma unroll
            for (int p = 0; p < 4; p++) {
                int f4 = p * 256 + tid;
                int r = f4 >> 3, c4 = (f4 & 7) * 4;
                pa[p] = *(const float4*)(Ab + (size_t)r * S_ + k0 + c4);
            }
#pragma unroll
            for (int p = 0; p < 2; p++) {
                int f4 = p * 256 + tid;
                int kr = f4 >> 4, c4 = (f4 & 15) * 4;
                pv[p] = *(const float4*)(Vb + (size_t)(k0 + kr) * D_ + c4);
            }
        }

#pragma unroll
        for (int kk = 0; kk < 32; kk += 8) {
            uint32_t af[2][4], bf[4][2];
#pragma unroll
            for (int mi = 0; mi < 2; mi++) {
                int mr = wm * 32 + mi * 16 + g;
                af[mi][0] = __float_as_uint(As[mr][kk + t]);
                af[mi][1] = __float_as_uint(As[mr + 8][kk + t]);
                af[mi][2] = __float_as_uint(As[mr][kk + t + 4]);
                af[mi][3] = __float_as_uint(As[mr + 8][kk + t + 4]);
            }
#pragma unroll
            for (int ni = 0; ni < 4; ni++) {
                int nr = wn * 32 + ni * 8 + g;
                bf[ni][0] = __float_as_uint(Vs[nr][kk + t]);
                bf[ni][1] = __float_as_uint(Vs[nr][kk + t + 4]);
            }
#pragma unroll
            for (int mi = 0; mi < 2; mi++)
#pragma unroll
                for (int ni = 0; ni < 4; ni++)
                    mma_tf32(acc[mi][ni], af[mi], bf[ni]);
        }
        __syncthreads();
    }

    float* Cb = g_C + ((size_t)b * S_ + m0) * D_ + h * HD_;
#pragma unroll
    for (int mi = 0; mi < 2; mi++) {
        int row = wm * 32 + mi * 16 + g;
#pragma unroll
        for (int ni = 0; ni < 4; ni++) {
            int col = wn * 32 + ni * 8 + 2 * t;
            float2 o0, o1;
            o0.x = f2tf(acc[mi][ni][0]); o0.y = f2tf(acc[mi][ni][1]);
            o1.x = f2tf(acc[mi][ni][2]); o1.y = f2tf(acc[mi][ni][3]);
            *(float2*)(Cb + (size_t)row * D_ + col)       = o0;
            *(float2*)(Cb + (size_t)(row + 8) * D_ + col) = o1;
        }
    }
}

// ---------------------------------------------------------------------------
// In-place row softmax over attn rows of length 2048 (float4 vectorized).
// ---------------------------------------------------------------------------
__global__ __launch_bounds__(256) void softmax_kernel(float* __restrict__ attn)
{
    size_t row = blockIdx.x;
    float4* p = (float4*)(attn + row * (size_t)S_);
    int t = threadIdx.x;

    float4 v[2];
    float m = -3.4e38f;
#pragma unroll
    for (int i = 0; i < 2; i++) {
        v[i] = p[t + i * 256];
        m = fmaxf(m, fmaxf(fmaxf(v[i].x, v[i].y), fmaxf(v[i].z, v[i].w)));
    }
    __shared__ float redm[8];
    __shared__ float reds[8];
#pragma unroll
    for (int o = 16; o > 0; o >>= 1) m = fmaxf(m, __shfl_xor_sync(0xffffffffu, m, o));
    if ((t & 31) == 0) redm[t >> 5] = m;
    __syncthreads();
    float mm = redm[0];
#pragma unroll
    for (int i = 1; i < 8; i++) mm = fmaxf(mm, redm[i]);

    float s = 0.f;
#pragma unroll
    for (int i = 0; i < 2; i++) {
        v[i].x = __expf(v[i].x - mm); v[i].y = __expf(v[i].y - mm);
        v[i].z = __expf(v[i].z - mm); v[i].w = __expf(v[i].w - mm);
        s += (v[i].x + v[i].y) + (v[i].z + v[i].w);
    }
#pragma unroll
    for (int o = 16; o > 0; o >>= 1) s += __shfl_xor_sync(0xffffffffu, s, o);
    if ((t & 31) == 0) reds[t >> 5] = s;
    __syncthreads();
    float ss = reds[0];
#pragma unroll
    for (int i = 1; i < 8; i++) ss += reds[i];
    float rinv = 1.0f / ss;
#pragma unroll
    for (int i = 0; i < 2; i++) {
        v[i].x *= rinv; v[i].y *= rinv; v[i].z *= rinv; v[i].w *= rinv;
        p[t + i * 256] = v[i];
    }
}

// ---------------------------------------------------------------------------
extern "C" void kernel_launch(void* const* d_in, const int* in_sizes, int n_in,
                              void* d_out, int out_size)
{
    const float* q  = (const float*)d_in[0];
    const float* k  = (const float*)d_in[1];
    const float* v  = (const float*)d_in[2];
    const float* Wq = (const float*)d_in[3];
    const float* bq = (const float*)d_in[4];
    const float* Wk = (const float*)d_in[5];
    const float* bk = (const float*)d_in[6];
    const float* Wv = (const float*)d_in[7];
    const float* bv = (const float*)d_in[8];
    const float* Wo = (const float*)d_in[9];
    const float* bo = (const float*)d_in[10];

    float* out  = (float*)d_out;
    float* attn = out + (size_t)MS_ * D_;   // tuple order: (output, attention)

    float *pQ, *pK, *pV, *pC, *pWT;
    cudaGetSymbolAddress((void**)&pQ, g_Q);
    cudaGetSymbolAddress((void**)&pK, g_K);
    cudaGetSymbolAddress((void**)&pV, g_V);
    cudaGetSymbolAddress((void**)&pC, g_C);
    cudaGetSymbolAddress((void**)&pWT, g_WT);

    float* WTq = pWT + 0 * (size_t)D_ * D_;
    float* WTk = pWT + 1 * (size_t)D_ * D_;
    float* WTv = pWT + 2 * (size_t)D_ * D_;
    float* WTo = pWT + 3 * (size_t)D_ * D_;

    dim3 tb(32, 8), tg(32, 32);
    transpose1024<<<tg, tb>>>(Wq, WTq);
    transpose1024<<<tg, tb>>>(Wk, WTk);
    transpose1024<<<tg, tb>>>(Wv, WTv);
    transpose1024<<<tg, tb>>>(Wo, WTo);

    qkv_gemm<<<dim3(8, 64, 3), 256>>>(q, k, v, WTq, WTk, WTv,
                                      bq, bk, bv, pQ, pK, pV);

    scores_mma<<<dim3(16, 16, 64), 256>>>(attn);
    softmax_kernel<<<B_ * H_ * S_, 256>>>(attn);
    context_mma<<<dim3(16, 64), 256>>>(attn);

    out_gemm<<<dim3(8, 64), 256>>>(pC, WTo, bo, out);
}

// round 6
// speedup vs baseline: 3.3222x; 1.2580x over previous
#include <cuda_runtime.h>
#include <math.h>
#include <stdint.h>

#define B_  4
#define S_  2048
#define D_  1024
#define H_  16
#define HD_ 64
#define MS_ (B_*S_)   // 8192

// Scratch (static device globals — no allocation)
__device__ float g_Q[(size_t)MS_ * D_];
__device__ float g_K[(size_t)MS_ * D_];
__device__ float g_V[(size_t)MS_ * D_];
__device__ float g_C[(size_t)MS_ * D_];
__device__ float g_WT[4][(size_t)D_ * D_];      // transposed + tf32-rounded weights
__device__ float2 g_ML[(size_t)B_ * H_ * S_];   // per-row (max, 1/sum)

// ---------------------------------------------------------------------------
// tf32 helpers (sm_80+ ISA — compiles for plain sm_103 target)
// ---------------------------------------------------------------------------
__device__ __forceinline__ float f2tf(float f) {
    uint32_t u;
    asm("cvt.rna.tf32.f32 %0, %1;" : "=r"(u) : "f"(f));
    return __uint_as_float(u);
}

__device__ __forceinline__ void mma_tf32(float* d, const uint32_t* a, const uint32_t* b) {
    asm volatile(
        "mma.sync.aligned.m16n8k8.row.col.f32.tf32.tf32.f32 "
        "{%0,%1,%2,%3}, {%4,%5,%6,%7}, {%8,%9}, {%0,%1,%2,%3};"
        : "+f"(d[0]), "+f"(d[1]), "+f"(d[2]), "+f"(d[3])
        : "r"(a[0]), "r"(a[1]), "r"(a[2]), "r"(a[3]),
          "r"(b[0]), "r"(b[1]));
}

// ===========================================================================
// Weight transposes (all 4 in one launch, grid.z selects) + tf32 pre-round
// ===========================================================================
__global__ __launch_bounds__(256) void transpose4(
    const float* __restrict__ W0, const float* __restrict__ W1,
    const float* __restrict__ W2, const float* __restrict__ W3,
    float* __restrict__ O0, float* __restrict__ O1,
    float* __restrict__ O2, float* __restrict__ O3)
{
    int z = blockIdx.z;
    const float* in = (z == 0) ? W0 : (z == 1) ? W1 : (z == 2) ? W2 : W3;
    float* out      = (z == 0) ? O0 : (z == 1) ? O1 : (z == 2) ? O2 : O3;

    __shared__ float t[32][33];
    int x = blockIdx.x * 32 + threadIdx.x;
    int y = blockIdx.y * 32 + threadIdx.y;
#pragma unroll
    for (int j = 0; j < 32; j += 8)
        t[threadIdx.y + j][threadIdx.x] = in[(size_t)(y + j) * D_ + x];
    __syncthreads();
    x = blockIdx.y * 32 + threadIdx.x;
    y = blockIdx.x * 32 + threadIdx.y;
#pragma unroll
    for (int j = 0; j < 32; j += 8)
        out[(size_t)(y + j) * D_ + x] = f2tf(t[threadIdx.x][threadIdx.y + j]);
}

// ===========================================================================
// Shared 128x128xK MMA mainloop, BK=32, register double-buffered.
// ===========================================================================
template<bool CVTA, bool CVTB>
__device__ __forceinline__ void gemm_main(
    const float* __restrict__ A, const float* __restrict__ BT,
    int K, int lda, int ldb,
    float (&As)[128][36], float (&Bs)[128][36],
    float (&acc)[4][4][4])
{
    int tid  = threadIdx.x;
    int lane = tid & 31, warp = tid >> 5;
    int g = lane >> 2, t = lane & 3;
    int wm = warp >> 2, wn = warp & 3;

    float4 pa[4], pb[4];
#pragma unroll
    for (int p = 0; p < 4; p++) {
        int f4 = p * 256 + tid;
        int r = f4 >> 3, c4 = (f4 & 7) * 4;
        pa[p] = *(const float4*)(A + (size_t)r * lda + c4);
        pb[p] = *(const float4*)(BT + (size_t)r * ldb + c4);
    }

    int NT = K / 32;
    for (int it = 0; it < NT; it++) {
#pragma unroll
        for (int p = 0; p < 4; p++) {
            int f4 = p * 256 + tid;
            int r = f4 >> 3, c4 = (f4 & 7) * 4;
            As[r][c4 + 0] = CVTA ? f2tf(pa[p].x) : pa[p].x;
            As[r][c4 + 1] = CVTA ? f2tf(pa[p].y) : pa[p].y;
            As[r][c4 + 2] = CVTA ? f2tf(pa[p].z) : pa[p].z;
            As[r][c4 + 3] = CVTA ? f2tf(pa[p].w) : pa[p].w;
            Bs[r][c4 + 0] = CVTB ? f2tf(pb[p].x) : pb[p].x;
            Bs[r][c4 + 1] = CVTB ? f2tf(pb[p].y) : pb[p].y;
            Bs[r][c4 + 2] = CVTB ? f2tf(pb[p].z) : pb[p].z;
            Bs[r][c4 + 3] = CVTB ? f2tf(pb[p].w) : pb[p].w;
        }
        __syncthreads();

        if (it + 1 < NT) {
            int k0 = (it + 1) * 32;
#pragma unroll
            for (int p = 0; p < 4; p++) {
                int f4 = p * 256 + tid;
                int r = f4 >> 3, c4 = (f4 & 7) * 4;
                pa[p] = *(const float4*)(A + (size_t)r * lda + k0 + c4);
                pb[p] = *(const float4*)(BT + (size_t)r * ldb + k0 + c4);
            }
        }

#pragma unroll
        for (int kk = 0; kk < 32; kk += 8) {
            uint32_t af[4][4], bf[4][2];
#pragma unroll
            for (int mi = 0; mi < 4; mi++) {
                int mr = wm * 64 + mi * 16 + g;
                af[mi][0] = __float_as_uint(As[mr][kk + t]);
                af[mi][1] = __float_as_uint(As[mr + 8][kk + t]);
                af[mi][2] = __float_as_uint(As[mr][kk + t + 4]);
                af[mi][3] = __float_as_uint(As[mr + 8][kk + t + 4]);
            }
#pragma unroll
            for (int ni = 0; ni < 4; ni++) {
                int nr = wn * 32 + ni * 8 + g;
                bf[ni][0] = __float_as_uint(Bs[nr][kk + t]);
                bf[ni][1] = __float_as_uint(Bs[nr][kk + t + 4]);
            }
#pragma unroll
            for (int mi = 0; mi < 4; mi++)
#pragma unroll
                for (int ni = 0; ni < 4; ni++)
                    mma_tf32(acc[mi][ni], af[mi], bf[ni]);
        }
        __syncthreads();
    }
}

// ===========================================================================
// Fused Q/K/V projection GEMMs (grid.z selects tensor).
// ===========================================================================
__global__ __launch_bounds__(256) void qkv_gemm(
    const float* __restrict__ Aq, const float* __restrict__ Ak,
    const float* __restrict__ Av,
    const float* __restrict__ Wq, const float* __restrict__ Wk,
    const float* __restrict__ Wv,
    const float* __restrict__ bq, const float* __restrict__ bk,
    const float* __restrict__ bv,
    float* __restrict__ Cq, float* __restrict__ Ck, float* __restrict__ Cv)
{
    __shared__ float As[128][36];
    __shared__ float Bs[128][36];

    int z = blockIdx.z;
    const float* A    = (z == 0) ? Aq : (z == 1) ? Ak : Av;
    const float* BT   = (z == 0) ? Wq : (z == 1) ? Wk : Wv;
    const float* bias = (z == 0) ? bq : (z == 1) ? bk : bv;
    float*       C    = (z == 0) ? Cq : (z == 1) ? Ck : Cv;

    int m0 = blockIdx.y * 128, n0 = blockIdx.x * 128;

    float acc[4][4][4];
#pragma unroll
    for (int i = 0; i < 4; i++)
#pragma unroll
        for (int j = 0; j < 4; j++)
#pragma unroll
            for (int r = 0; r < 4; r++) acc[i][j][r] = 0.f;

    gemm_main<true, false>(A + (size_t)m0 * D_, BT + (size_t)n0 * D_,
                           D_, D_, D_, As, Bs, acc);

    int lane = threadIdx.x & 31, warp = threadIdx.x >> 5;
    int g = lane >> 2, t = lane & 3;
    int wm = warp >> 2, wn = warp & 3;
#pragma unroll
    for (int mi = 0; mi < 4; mi++) {
        int row = m0 + wm * 64 + mi * 16 + g;
#pragma unroll
        for (int ni = 0; ni < 4; ni++) {
            int col = n0 + wn * 32 + ni * 8 + 2 * t;
            float2 b2 = *(const float2*)(bias + col);
            float2 o0, o1;
            o0.x = f2tf(acc[mi][ni][0] + b2.x); o0.y = f2tf(acc[mi][ni][1] + b2.y);
            o1.x = f2tf(acc[mi][ni][2] + b2.x); o1.y = f2tf(acc[mi][ni][3] + b2.y);
            *(float2*)(C + (size_t)row * D_ + col)       = o0;
            *(float2*)(C + (size_t)(row + 8) * D_ + col) = o1;
        }
    }
}

// ===========================================================================
// Output projection GEMM.
// ===========================================================================
__global__ __launch_bounds__(256) void out_gemm(
    const float* __restrict__ A, const float* __restrict__ BT,
    const float* __restrict__ bias, float* __restrict__ C)
{
    __shared__ float As[128][36];
    __shared__ float Bs[128][36];

    int m0 = blockIdx.y * 128, n0 = blockIdx.x * 128;

    float acc[4][4][4];
#pragma unroll
    for (int i = 0; i < 4; i++)
#pragma unroll
        for (int j = 0; j < 4; j++)
#pragma unroll
            for (int r = 0; r < 4; r++) acc[i][j][r] = 0.f;

    gemm_main<false, false>(A + (size_t)m0 * D_, BT + (size_t)n0 * D_,
                            D_, D_, D_, As, Bs, acc);

    int lane = threadIdx.x & 31, warp = threadIdx.x >> 5;
    int g = lane >> 2, t = lane & 3;
    int wm = warp >> 2, wn = warp & 3;
#pragma unroll
    for (int mi = 0; mi < 4; mi++) {
        int row = m0 + wm * 64 + mi * 16 + g;
#pragma unroll
        for (int ni = 0; ni < 4; ni++) {
            int col = n0 + wn * 32 + ni * 8 + 2 * t;
            float2 b2 = *(const float2*)(bias + col);
            float2 o0, o1;
            o0.x = acc[mi][ni][0] + b2.x; o0.y = acc[mi][ni][1] + b2.y;
            o1.x = acc[mi][ni][2] + b2.x; o1.y = acc[mi][ni][3] + b2.y;
            *(float2*)(C + (size_t)row * D_ + col)       = o0;
            *(float2*)(C + (size_t)(row + 8) * D_ + col) = o1;
        }
    }
}

// ===========================================================================
// Scores + online softmax stats: CTA = 128 queries x all 2048 keys, one (b,h).
// Writes raw scaled scores to attn; per-row (max, 1/sum) to g_ML.
// grid (16, 64), 256 threads.
// ===========================================================================
__global__ __launch_bounds__(256) void scores_ml(float* __restrict__ attn)
{
    __shared__ float As[128][68];   // Q [q][hd]
    __shared__ float Bs[128][68];   // K tile [key][hd]
    __shared__ float Ms[128][4];
    __shared__ float Ls[128][4];

    int tid  = threadIdx.x;
    int lane = tid & 31, warp = tid >> 5;
    int g = lane >> 2, t = lane & 3;
    int wm = warp >> 2, wn = warp & 3;

    int bh = blockIdx.y;
    int b = bh >> 4, h = bh & 15;
    int q0 = blockIdx.x * 128;

    const float* Qb = g_Q + ((size_t)b * S_ + q0) * D_ + h * HD_;
    const float* Kb = g_K + (size_t)b * S_ * D_ + h * HD_;

    // load Q tile 128 x 64 (pre-rounded tf32 in g_Q)
#pragma unroll
    for (int p = 0; p < 8; p++) {
        int f4 = p * 256 + tid;
        int r = f4 >> 4, c4 = (f4 & 15) * 4;
        *(float4*)(&As[r][c4]) = *(const float4*)(Qb + (size_t)r * D_ + c4);
    }

    float m8[8], l8[8];
#pragma unroll
    for (int i = 0; i < 8; i++) { m8[i] = -3.0e38f; l8[i] = 0.f; }

    float4 pk[8];
#pragma unroll
    for (int p = 0; p < 8; p++) {
        int f4 = p * 256 + tid;
        int r = f4 >> 4, c4 = (f4 & 15) * 4;
        pk[p] = *(const float4*)(Kb + (size_t)r * D_ + c4);
    }

    const float scale = 0.125f;
    size_t base = (size_t)bh * S_ * S_;

    for (int kt = 0; kt < 16; kt++) {
#pragma unroll
        for (int p = 0; p < 8; p++) {
            int f4 = p * 256 + tid;
            int r = f4 >> 4, c4 = (f4 & 15) * 4;
            *(float4*)(&Bs[r][c4]) = pk[p];
        }
        __syncthreads();

        if (kt + 1 < 16) {
            const float* Kt = Kb + (size_t)(kt + 1) * 128 * D_;
#pragma unroll
            for (int p = 0; p < 8; p++) {
                int f4 = p * 256 + tid;
                int r = f4 >> 4, c4 = (f4 & 15) * 4;
                pk[p] = *(const float4*)(Kt + (size_t)r * D_ + c4);
            }
        }

        float acc[4][4][4];
#pragma unroll
        for (int i = 0; i < 4; i++)
#pragma unroll
            for (int j = 0; j < 4; j++)
#pragma unroll
                for (int r = 0; r < 4; r++) acc[i][j][r] = 0.f;

#pragma unroll
        for (int kk = 0; kk < 64; kk += 8) {
            uint32_t af[4][4], bf[4][2];
#pragma unroll
            for (int mi = 0; mi < 4; mi++) {
                int mr = wm * 64 + mi * 16 + g;
                af[mi][0] = __float_as_uint(As[mr][kk + t]);
                af[mi][1] = __float_as_uint(As[mr + 8][kk + t]);
                af[mi][2] = __float_as_uint(As[mr][kk + t + 4]);
                af[mi][3] = __float_as_uint(As[mr + 8][kk + t + 4]);
            }
#pragma unroll
            for (int ni = 0; ni < 4; ni++) {
                int nr = wn * 32 + ni * 8 + g;
                bf[ni][0] = __float_as_uint(Bs[nr][kk + t]);
                bf[ni][1] = __float_as_uint(Bs[nr][kk + t + 4]);
            }
#pragma unroll
            for (int mi = 0; mi < 4; mi++)
#pragma unroll
                for (int ni = 0; ni < 4; ni++)
                    mma_tf32(acc[mi][ni], af[mi], bf[ni]);
        }

        // scale + store raw + update online stats
#pragma unroll
        for (int mi = 0; mi < 4; mi++) {
            int row = wm * 64 + mi * 16 + g;
#pragma unroll
            for (int ni = 0; ni < 4; ni++) {
                int col = kt * 128 + wn * 32 + ni * 8 + 2 * t;
#pragma unroll
                for (int r = 0; r < 4; r++) acc[mi][ni][r] *= scale;
                float2 o0, o1;
                o0.x = acc[mi][ni][0]; o0.y = acc[mi][ni][1];
                o1.x = acc[mi][ni][2]; o1.y = acc[mi][ni][3];
                *(float2*)(attn + base + (size_t)(q0 + row) * S_ + col)     = o0;
                *(float2*)(attn + base + (size_t)(q0 + row + 8) * S_ + col) = o1;
            }
#pragma unroll
            for (int half = 0; half < 2; half++) {
                int ti = mi * 2 + half;
                float v[8];
#pragma unroll
                for (int ni = 0; ni < 4; ni++) {
                    v[ni * 2 + 0] = acc[mi][ni][half * 2 + 0];
                    v[ni * 2 + 1] = acc[mi][ni][half * 2 + 1];
                }
                float tm = v[0];
#pragma unroll
                for (int i = 1; i < 8; i++) tm = fmaxf(tm, v[i]);
                float mn = fmaxf(m8[ti], tm);
                float l = l8[ti] * __expf(m8[ti] - mn);
#pragma unroll
                for (int i = 0; i < 8; i++) l += __expf(v[i] - mn);
                m8[ti] = mn; l8[ti] = l;
            }
        }
        __syncthreads();
    }

    // reduce (m,l) over t (lanes within quad share rows)
#pragma unroll
    for (int ti = 0; ti < 8; ti++) {
        float m = m8[ti], l = l8[ti];
#pragma unroll
        for (int off = 1; off <= 2; off <<= 1) {
            float mo = __shfl_xor_sync(0xffffffffu, m, off);
            float lo = __shfl_xor_sync(0xffffffffu, l, off);
            float mn = fmaxf(m, mo);
            l = l * __expf(m - mn) + lo * __expf(mo - mn);
            m = mn;
        }
        m8[ti] = m; l8[ti] = l;
    }
    if (t == 0) {
#pragma unroll
        for (int ti = 0; ti < 8; ti++) {
            int mi = ti >> 1, half = ti & 1;
            int row = wm * 64 + mi * 16 + g + half * 8;
            Ms[row][wn] = m8[ti]; Ls[row][wn] = l8[ti];
        }
    }
    __syncthreads();
    if (tid < 128) {
        float m = Ms[tid][0], l = Ls[tid][0];
#pragma unroll
        for (int i = 1; i < 4; i++) {
            float mo = Ms[tid][i], lo = Ls[tid][i];
            float mn = fmaxf(m, mo);
            l = l * __expf(m - mn) + lo * __expf(mo - mn);
            m = mn;
        }
        g_ML[(size_t)bh * S_ + q0 + tid] = make_float2(m, 1.0f / l);
    }
}

// ===========================================================================
// Normalize + write probs + context: p = exp(s-m)*rinv; attn <- p; C = P @ V.
// 128(q) x 64(hd) tile, BK=32, double-buffered. grid (16, 64).
// ===========================================================================
__global__ __launch_bounds__(256) void context_norm(float* __restrict__ attn)
{
    __shared__ float As[128][36];   // probs [q][kpos]
    __shared__ float Vs[64][36];    // V^T   [hd][kpos]
    __shared__ float2 MLs[128];

    int tid  = threadIdx.x;
    int lane = tid & 31, warp = tid >> 5;
    int g = lane >> 2, t = lane & 3;
    int wm = warp >> 1, wn = warp & 1;   // 4 x 2

    int bh = blockIdx.y;
    int b = bh >> 4, h = bh & 15;
    int m0 = blockIdx.x * 128;
    float* Ab = attn + (size_t)bh * S_ * S_ + (size_t)m0 * S_;
    const float* Vb = g_V + (size_t)b * S_ * D_ + h * HD_;

    if (tid < 128) MLs[tid] = g_ML[(size_t)bh * S_ + m0 + tid];

    float acc[2][4][4];
#pragma unroll
    for (int i = 0; i < 2; i++)
#pragma unroll
        for (int j = 0; j < 4; j++)
#pragma unroll
            for (int r = 0; r < 4; r++) acc[i][j][r] = 0.f;

    float4 pa[4], pv[2];
#pragma unroll
    for (int p = 0; p < 4; p++) {
        int f4 = p * 256 + tid;
        int r = f4 >> 3, c4 = (f4 & 7) * 4;
        pa[p] = *(const float4*)(Ab + (size_t)r * S_ + c4);
    }
#pragma unroll
    for (int p = 0; p < 2; p++) {
        int f4 = p * 256 + tid;
        int kr = f4 >> 4, c4 = (f4 & 15) * 4;
        pv[p] = *(const float4*)(Vb + (size_t)kr * D_ + c4);
    }
    __syncthreads();   // MLs visible

    for (int it = 0; it < S_ / 32; it++) {
        int k0c = it * 32;
#pragma unroll
        for (int p = 0; p < 4; p++) {
            int f4 = p * 256 + tid;
            int r = f4 >> 3, c4 = (f4 & 7) * 4;
            float2 ml = MLs[r];
            float4 pr;
            pr.x = __expf(pa[p].x - ml.x) * ml.y;
            pr.y = __expf(pa[p].y - ml.x) * ml.y;
            pr.z = __expf(pa[p].z - ml.x) * ml.y;
            pr.w = __expf(pa[p].w - ml.x) * ml.y;
            *(float4*)(Ab + (size_t)r * S_ + k0c + c4) = pr;   // final probs
            As[r][c4 + 0] = f2tf(pr.x); As[r][c4 + 1] = f2tf(pr.y);
            As[r][c4 + 2] = f2tf(pr.z); As[r][c4 + 3] = f2tf(pr.w);
        }
#pragma unroll
        for (int p = 0; p < 2; p++) {
            int f4 = p * 256 + tid;
            int kr = f4 >> 4, c4 = (f4 & 15) * 4;
            Vs[c4 + 0][kr] = pv[p].x; Vs[c4 + 1][kr] = pv[p].y;
            Vs[c4 + 2][kr] = pv[p].z; Vs[c4 + 3][kr] = pv[p].w;
        }
        __syncthreads();

        if (it + 1 < S_ / 32) {
            int k0 = k0c + 32;
#pragma unroll
            for (int p = 0; p < 4; p++) {
                int f4 = p * 256 + tid;
                int r = f4 >> 3, c4 = (f4 & 7) * 4;
                pa[p] = *(const float4*)(Ab + (size_t)r * S_ + k0 + c4);
            }
#pragma unroll
            for (int p = 0; p < 2; p++) {
                int f4 = p * 256 + tid;
                int kr = f4 >> 4, c4 = (f4 & 15) * 4;
                pv[p] = *(const float4*)(Vb + (size_t)(k0 + kr) * D_ + c4);
            }
        }

#pragma unroll
        for (int kk = 0; kk < 32; kk += 8) {
            uint32_t af[2][4], bf[4][2];
#pragma unroll
            for (int mi = 0; mi < 2; mi++) {
                int mr = wm * 32 + mi * 16 + g;
                af[mi][0] = __float_as_uint(As[mr][kk + t]);
                af[mi][1] = __float_as_uint(As[mr + 8][kk + t]);
                af[mi][2] = __float_as_uint(As[mr][kk + t + 4]);
                af[mi][3] = __float_as_uint(As[mr + 8][kk + t + 4]);
            }
#pragma unroll
            for (int ni = 0; ni < 4; ni++) {
                int nr = wn * 32 + ni * 8 + g;
                bf[ni][0] = __float_as_uint(Vs[nr][kk + t]);
                bf[ni][1] = __float_as_uint(Vs[nr][kk + t + 4]);
            }
#pragma unroll
            for (int mi = 0; mi < 2; mi++)
#pragma unroll
                for (int ni = 0; ni < 4; ni++)
                    mma_tf32(acc[mi][ni], af[mi], bf[ni]);
        }
        __syncthreads();
    }

    float* Cb = g_C + ((size_t)b * S_ + m0) * D_ + h * HD_;
#pragma unroll
    for (int mi = 0; mi < 2; mi++) {
        int row = wm * 32 + mi * 16 + g;
#pragma unroll
        for (int ni = 0; ni < 4; ni++) {
            int col = wn * 32 + ni * 8 + 2 * t;
            float2 o0, o1;
            o0.x = f2tf(acc[mi][ni][0]); o0.y = f2tf(acc[mi][ni][1]);
            o1.x = f2tf(acc[mi][ni][2]); o1.y = f2tf(acc[mi][ni][3]);
            *(float2*)(Cb + (size_t)row * D_ + col)       = o0;
            *(float2*)(Cb + (size_t)(row + 8) * D_ + col) = o1;
        }
    }
}

// ---------------------------------------------------------------------------
extern "C" void kernel_launch(void* const* d_in, const int* in_sizes, int n_in,
                              void* d_out, int out_size)
{
    const float* q  = (const float*)d_in[0];
    const float* k  = (const float*)d_in[1];
    const float* v  = (const float*)d_in[2];
    const float* Wq = (const float*)d_in[3];
    const float* bq = (const float*)d_in[4];
    const float* Wk = (const float*)d_in[5];
    const float* bk = (const float*)d_in[6];
    const float* Wv = (const float*)d_in[7];
    const float* bv = (const float*)d_in[8];
    const float* Wo = (const float*)d_in[9];
    const float* bo = (const float*)d_in[10];

    float* out  = (float*)d_out;
    float* attn = out + (size_t)MS_ * D_;   // tuple order: (output, attention)

    float *pQ, *pK, *pV, *pC, *pWT;
    cudaGetSymbolAddress((void**)&pQ, g_Q);
    cudaGetSymbolAddress((void**)&pK, g_K);
    cudaGetSymbolAddress((void**)&pV, g_V);
    cudaGetSymbolAddress((void**)&pC, g_C);
    cudaGetSymbolAddress((void**)&pWT, g_WT);

    float* WTq = pWT + 0 * (size_t)D_ * D_;
    float* WTk = pWT + 1 * (size_t)D_ * D_;
    float* WTv = pWT + 2 * (size_t)D_ * D_;
    float* WTo = pWT + 3 * (size_t)D_ * D_;

    transpose4<<<dim3(32, 32, 4), dim3(32, 8)>>>(Wq, Wk, Wv, Wo,
                                                 WTq, WTk, WTv, WTo);

    qkv_gemm<<<dim3(8, 64, 3), 256>>>(q, k, v, WTq, WTk, WTv,
                                      bq, bk, bv, pQ, pK, pV);

    scores_ml<<<dim3(16, 64), 256>>>(attn);
    context_norm<<<dim3(16, 64), 256>>>(attn);

    out_gemm<<<dim3(8, 64), 256>>>(pC, WTo, bo, out);
}